// round 1
// baseline (speedup 1.0000x reference)
#include <cuda_runtime.h>
#include <math.h>

#define B 32
#define T 2048
#define E 512
#define D 1024
#define H 128

#define TT 32      // t-tile per block in k_erg
#define EC 32      // e-chunk per smem stage
#define TS 16      // t-splits in context pass

// ---- scratch (no allocations allowed) ----
__device__ float g_dec[B * H];                 // b_enc + decoder projection
__device__ float g_erg[B * T];                 // pre-softmax logits
__device__ float g_ctx_part[TS][B][E];         // context partials

// ---------------------------------------------------------------------------
// Kernel 1: dec[b,h] = b_enc[h] + sum_d state[b,d] * W_dec[d,h]
// ---------------------------------------------------------------------------
__global__ void k_dec(const float* __restrict__ ds,
                      const float* __restrict__ Wdec,
                      const float* __restrict__ benc) {
    int b = blockIdx.x;
    int h = threadIdx.x;
    float acc = benc[h];
    const float* dsr = ds + b * D;
#pragma unroll 4
    for (int d = 0; d < D; d++) {
        acc = fmaf(dsr[d], Wdec[d * H + h], acc);
    }
    g_dec[b * H + h] = acc;
}

// ---------------------------------------------------------------------------
// Kernel 2: the big GEMM + tanh + dot(w_w) fused epilogue.
// Block: 256 threads = 8 ty-groups (4 t each) x 32 tx-lanes (4 h each).
// ---------------------------------------------------------------------------
__global__ __launch_bounds__(256, 4)
void k_erg(const float* __restrict__ enc,
           const float* __restrict__ Wenc,
           const float* __restrict__ ww,
           const float* __restrict__ wbp) {
    __shared__ float sE[EC][TT];   // enc tile, transposed: [e][t]
    __shared__ float sW[EC][H];    // W tile: [e][h] (same order as global)

    const int b  = blockIdx.y;
    const int t0 = blockIdx.x * TT;
    const int tid = threadIdx.x;
    const int tx = tid & 31;       // lane: h-group
    const int ty = tid >> 5;       // warp: t-group

    float acc[4][4];
#pragma unroll
    for (int i = 0; i < 4; i++)
#pragma unroll
        for (int j = 0; j < 4; j++) acc[i][j] = 0.f;

    // global load indices for the enc tile (one float4 per thread)
    const int lt = tid >> 3;            // 0..31 (t within tile)
    const int le = (tid & 7) * 4;       // 0,4,...,28 (e within chunk)
    const float* enc_base = enc + ((size_t)b * T + t0 + lt) * E + le;

    const float4* wsrc = (const float4*)(Wenc);   // [E*H/4]
    float4* wdst = (float4*)(&sW[0][0]);

    for (int ec = 0; ec < E; ec += EC) {
        // enc tile -> transposed smem
        float4 v = *(const float4*)(enc_base + ec);
        sE[le + 0][lt] = v.x;
        sE[le + 1][lt] = v.y;
        sE[le + 2][lt] = v.z;
        sE[le + 3][lt] = v.w;
        // W tile: rows ec..ec+31 are contiguous (EC*H = 4096 floats = 1024 float4)
        const float4* ws = wsrc + (size_t)ec * H / 4;
#pragma unroll
        for (int k = 0; k < 4; k++) {
            wdst[tid + k * 256] = ws[tid + k * 256];
        }
        __syncthreads();

#pragma unroll
        for (int e = 0; e < EC; e++) {
            float4 a = *(const float4*)(&sE[e][ty * 4]);   // broadcast within warp
            float4 w = *(const float4*)(&sW[e][tx * 4]);
            float av[4] = {a.x, a.y, a.z, a.w};
            float wv[4] = {w.x, w.y, w.z, w.w};
#pragma unroll
            for (int i = 0; i < 4; i++)
#pragma unroll
                for (int j = 0; j < 4; j++)
                    acc[i][j] = fmaf(av[i], wv[j], acc[i][j]);
        }
        __syncthreads();
    }

    // epilogue: + dec, tanh, * w_w, reduce over h (warp covers all 128 h)
    const float* db = g_dec + b * H + tx * 4;
    float dec4[4] = {db[0], db[1], db[2], db[3]};
    const float* wwp = ww + tx * 4;
    float w4[4] = {wwp[0], wwp[1], wwp[2], wwp[3]};
    const float wb = wbp[0];

#pragma unroll
    for (int i = 0; i < 4; i++) {
        float s = 0.f;
#pragma unroll
        for (int j = 0; j < 4; j++)
            s = fmaf(tanhf(acc[i][j] + dec4[j]), w4[j], s);
#pragma unroll
        for (int o = 16; o; o >>= 1)
            s += __shfl_xor_sync(0xffffffffu, s, o);
        if (tx == 0)
            g_erg[b * T + t0 + ty * 4 + i] = s + wb;
    }
}

// ---------------------------------------------------------------------------
// Kernel 3: masked softmax over T per batch row. Writes weights to d_out.
// ---------------------------------------------------------------------------
__global__ __launch_bounds__(256)
void k_softmax(const int* __restrict__ lens, float* __restrict__ wout) {
    const int b = blockIdx.x;
    const int len = lens[b];
    const int tid = threadIdx.x;
    const int lane = tid & 31, wid = tid >> 5;
    __shared__ float sh[8];

    // max over valid positions
    float m = -INFINITY;
#pragma unroll
    for (int k = 0; k < T / 256; k++) {
        int t = tid + k * 256;
        if (t < len) m = fmaxf(m, g_erg[b * T + t]);
    }
#pragma unroll
    for (int o = 16; o; o >>= 1) m = fmaxf(m, __shfl_xor_sync(0xffffffffu, m, o));
    if (lane == 0) sh[wid] = m;
    __syncthreads();
    m = (lane < 8) ? sh[lane] : -INFINITY;
#pragma unroll
    for (int o = 4; o; o >>= 1) m = fmaxf(m, __shfl_xor_sync(0xffffffffu, m, o));
    m = __shfl_sync(0xffffffffu, m, 0);   // broadcast within warp 0
    if (tid == 0) sh[0] = m;
    __syncthreads();
    m = sh[0];
    __syncthreads();

    // exp + sum
    float v[T / 256];
    float sum = 0.f;
#pragma unroll
    for (int k = 0; k < T / 256; k++) {
        int t = tid + k * 256;
        v[k] = (t < len) ? expf(g_erg[b * T + t] - m) : 0.f;
        sum += v[k];
    }
#pragma unroll
    for (int o = 16; o; o >>= 1) sum += __shfl_xor_sync(0xffffffffu, sum, o);
    if (lane == 0) sh[wid] = sum;
    __syncthreads();
    sum = (lane < 8) ? sh[lane] : 0.f;
#pragma unroll
    for (int o = 4; o; o >>= 1) sum += __shfl_xor_sync(0xffffffffu, sum, o);
    if (tid == 0) sh[0] = sum;
    __syncthreads();
    const float inv = 1.f / sh[0];

#pragma unroll
    for (int k = 0; k < T / 256; k++) {
        int t = tid + k * 256;
        wout[b * T + t] = v[k] * inv;
    }
}

// ---------------------------------------------------------------------------
// Kernel 4a: context partials over T-splits (deterministic, no atomics)
// grid (B, TS), 512 threads = one per e
// ---------------------------------------------------------------------------
__global__ __launch_bounds__(512)
void k_ctx_part(const float* __restrict__ enc, const float* __restrict__ wgt) {
    const int b = blockIdx.x;
    const int ts = blockIdx.y;
    const int e = threadIdx.x;
    const int t0 = ts * (T / TS);
    __shared__ float sw[T / TS];
    if (threadIdx.x < T / TS)
        sw[threadIdx.x] = wgt[b * T + t0 + threadIdx.x];
    __syncthreads();

    float acc = 0.f;
    const float* p = enc + ((size_t)b * T + t0) * E + e;
#pragma unroll 8
    for (int t = 0; t < T / TS; t++)
        acc = fmaf(sw[t], p[(size_t)t * E], acc);
    g_ctx_part[ts][b][e] = acc;
}

// Kernel 4b: reduce partials -> context
__global__ __launch_bounds__(512)
void k_ctx_reduce(float* __restrict__ ctx) {
    const int b = blockIdx.x;
    const int e = threadIdx.x;
    float s = 0.f;
#pragma unroll
    for (int k = 0; k < TS; k++) s += g_ctx_part[k][b][e];
    ctx[b * E + e] = s;
}

// ---------------------------------------------------------------------------
extern "C" void kernel_launch(void* const* d_in, const int* in_sizes, int n_in,
                              void* d_out, int out_size) {
    const float* enc  = (const float*)d_in[0];   // [B,T,E]
    const int*   lens = (const int*)  d_in[1];   // [B]
    const float* ds   = (const float*)d_in[2];   // [B,D]
    // d_in[3] = mask (bool) — unused; rebuilt from src_lens
    const float* Wenc = (const float*)d_in[4];   // [E,H]
    const float* benc = (const float*)d_in[5];   // [H]
    const float* Wdec = (const float*)d_in[6];   // [D,H]
    const float* ww   = (const float*)d_in[7];   // [H,1]
    const float* wb   = (const float*)d_in[8];   // [1]

    float* ctx = (float*)d_out;           // [B,E]
    float* wgt = (float*)d_out + B * E;   // [B,T]

    k_dec<<<B, H>>>(ds, Wdec, benc);
    k_erg<<<dim3(T / TT, B), 256>>>(enc, Wenc, ww, wb);
    k_softmax<<<B, 256>>>(lens, wgt);
    k_ctx_part<<<dim3(B, TS), 512>>>(enc, wgt);
    k_ctx_reduce<<<B, E>>>(ctx);
}

// round 3
// speedup vs baseline: 2.6472x; 2.6472x over previous
#include <cuda_runtime.h>
#include <cuda_bf16.h>
#include <math.h>
#include <stdint.h>

#define B 32
#define T 2048
#define E 512
#define D 1024
#define H 128

#define TS 32      // t-splits in context pass
#define KC 32      // k-chunk (e) per smem stage in k_erg
#define ROWU 20    // padded row stride in u32 (32 bf16 data + pad) - bank-conflict-free

// ---- scratch (no allocations allowed) ----
__device__ float g_dec[B * H];
__device__ float g_erg[B * T];
__device__ float g_ctx_part[TS][B][E];
__device__ __nv_bfloat16 g_wbf_hi[H * E];   // W_enc^T hi part: [h][e]
__device__ __nv_bfloat16 g_wbf_lo[H * E];   // residual

// ===========================================================================
// helpers
// ===========================================================================
__device__ __forceinline__ uint32_t smem_u32(const void* p) {
    uint32_t a;
    asm("{ .reg .u64 t; cvta.to.shared.u64 t, %1; cvt.u32.u64 %0, t; }"
        : "=r"(a) : "l"(p));
    return a;
}
__device__ __forceinline__ void cp_async16(uint32_t dst, const void* src) {
    asm volatile("cp.async.ca.shared.global [%0], [%1], 16;"
                 :: "r"(dst), "l"(src) : "memory");
}
__device__ __forceinline__ void cp_commit() {
    asm volatile("cp.async.commit_group;" ::: "memory");
}
__device__ __forceinline__ void cp_wait0() {
    asm volatile("cp.async.wait_group 0;" ::: "memory");
}
// pack two f32 into bf16x2 (x -> low half), plus residual pair
__device__ __forceinline__ void split2(float x, float y, uint32_t& hi, uint32_t& lo) {
    asm("cvt.rn.bf16x2.f32 %0, %1, %2;" : "=r"(hi) : "f"(y), "f"(x));
    float hx = __uint_as_float(hi << 16);
    float hy = __uint_as_float(hi & 0xFFFF0000u);
    float lx = x - hx, ly = y - hy;
    asm("cvt.rn.bf16x2.f32 %0, %1, %2;" : "=r"(lo) : "f"(ly), "f"(lx));
}
__device__ __forceinline__ void mma_bf16(float* c, const uint32_t* a,
                                         uint32_t b0, uint32_t b1) {
    asm volatile(
        "mma.sync.aligned.m16n8k16.row.col.f32.bf16.bf16.f32 "
        "{%0,%1,%2,%3}, {%4,%5,%6,%7}, {%8,%9}, {%0,%1,%2,%3};"
        : "+f"(c[0]), "+f"(c[1]), "+f"(c[2]), "+f"(c[3])
        : "r"(a[0]), "r"(a[1]), "r"(a[2]), "r"(a[3]), "r"(b0), "r"(b1));
}

// ===========================================================================
// k_wprep: W_enc [E][H] -> bf16 hi/lo transposed [H][E]
// ===========================================================================
__global__ void k_wprep(const float* __restrict__ W) {
    __shared__ float tile[32][33];
    const int e0 = blockIdx.x * 32, h0 = blockIdx.y * 32;
    const int tx = threadIdx.x, ty = threadIdx.y;
    tile[ty][tx] = W[(size_t)(e0 + ty) * H + h0 + tx];
    __syncthreads();
    float v = tile[tx][ty];            // = W[e0+tx][h0+ty]
    __nv_bfloat16 hb = __float2bfloat16_rn(v);
    float lo = v - __bfloat162float(hb);
    g_wbf_hi[(size_t)(h0 + ty) * E + e0 + tx] = hb;
    g_wbf_lo[(size_t)(h0 + ty) * E + e0 + tx] = __float2bfloat16_rn(lo);
}

// ===========================================================================
// k_dec: dec[b,h] = b_enc[h] + sum_d state[b,d] * W_dec[d,h]
// ===========================================================================
__global__ __launch_bounds__(1024)
void k_dec(const float* __restrict__ ds, const float* __restrict__ Wdec,
           const float* __restrict__ benc) {
    __shared__ float s[8][128];
    const int b = blockIdx.x;
    const int h = threadIdx.x, ty = threadIdx.y;
    float acc = 0.f;
    const float* dsr = ds + b * D + ty * 128;
    const float* wp = Wdec + (size_t)(ty * 128) * H + h;
#pragma unroll 8
    for (int d = 0; d < 128; d++)
        acc = fmaf(dsr[d], wp[(size_t)d * H], acc);
    s[ty][h] = acc;
    __syncthreads();
    if (ty == 0) {
        float t = benc[h];
#pragma unroll
        for (int k = 0; k < 8; k++) t += s[k][h];
        g_dec[b * H + h] = t;
    }
}

// ===========================================================================
// k_erg: HMMA bf16 3-split GEMM [128t x 128h x 512e] per CTA + fused epilogue
// grid 512, block 256 (8 warps; warp = 32t x 64h)
// ===========================================================================
__global__ __launch_bounds__(256, 2)
void k_erg(const float* __restrict__ enc, const float* __restrict__ ww,
           const float* __restrict__ wbp) {
    __shared__ uint32_t sAhi[128 * ROWU];
    __shared__ uint32_t sAlo[128 * ROWU];
    __shared__ uint32_t sWhi[128 * ROWU];
    __shared__ uint32_t sWlo[128 * ROWU];
    __shared__ float s_dec[128], s_ww[128], s_erg[128];

    const int tid = threadIdx.x;
    const int w = tid >> 5, lane = tid & 31;
    const int g = lane >> 2, tig = lane & 3;
    const int b = blockIdx.x >> 4;
    const int t0 = (blockIdx.x & 15) * 128;
    const int mrow0 = (w & 3) * 32;
    const int ncol0 = (w >> 2) * 64;

    if (tid < 128) {
        s_dec[tid] = g_dec[b * H + tid];
        s_ww[tid] = ww[tid];
    }

    const uint32_t sWhi_b = smem_u32(sWhi);
    const uint32_t sWlo_b = smem_u32(sWlo);

    const int arow = tid >> 1, ahalf = tid & 1;
    const float* aptr = enc + (size_t)(b * T + t0 + arow) * E + ahalf * 16;

    float acc[2][8][4];
#pragma unroll
    for (int mt = 0; mt < 2; mt++)
#pragma unroll
        for (int nt = 0; nt < 8; nt++)
#pragma unroll
            for (int j = 0; j < 4; j++) acc[mt][nt][j] = 0.f;

    for (int c = 0; c < 16; c++) {
        // --- W tiles via cp.async (bf16, no conversion needed) ---
#pragma unroll
        for (int i = 0; i < 2; i++) {
            int linear = tid + i * 256;          // 0..511
            int row = linear >> 2, seg = linear & 3;
            size_t goff = (size_t)row * E + c * KC + seg * 8;
            uint32_t soff = (uint32_t)(row * ROWU + seg * 4) * 4;
            cp_async16(sWhi_b + soff, g_wbf_hi + goff);
            cp_async16(sWlo_b + soff, g_wbf_lo + goff);
        }
        cp_commit();

        // --- A tile: load f32, split to bf16 hi/lo, store padded smem ---
        const float* ap = aptr + c * KC;
        float4 f0 = *(const float4*)(ap);
        float4 f1 = *(const float4*)(ap + 4);
        float4 f2 = *(const float4*)(ap + 8);
        float4 f3 = *(const float4*)(ap + 12);
        uint32_t h0, h1, h2, h3, h4, h5, h6, h7;
        uint32_t l0, l1, l2, l3, l4, l5, l6, l7;
        split2(f0.x, f0.y, h0, l0); split2(f0.z, f0.w, h1, l1);
        split2(f1.x, f1.y, h2, l2); split2(f1.z, f1.w, h3, l3);
        split2(f2.x, f2.y, h4, l4); split2(f2.z, f2.w, h5, l5);
        split2(f3.x, f3.y, h6, l6); split2(f3.z, f3.w, h7, l7);
        uint4* dh = (uint4*)&sAhi[arow * ROWU + ahalf * 8];
        uint4* dl = (uint4*)&sAlo[arow * ROWU + ahalf * 8];
        dh[0] = make_uint4(h0, h1, h2, h3);
        dh[1] = make_uint4(h4, h5, h6, h7);
        dl[0] = make_uint4(l0, l1, l2, l3);
        dl[1] = make_uint4(l4, l5, l6, l7);

        cp_wait0();
        __syncthreads();

        // --- compute: 2 k-steps of 16 ---
#pragma unroll
        for (int ks = 0; ks < 2; ks++) {
            uint32_t ah[2][4], al[2][4];
#pragma unroll
            for (int mt = 0; mt < 2; mt++) {
                int base = (mrow0 + mt * 16 + g) * ROWU + ks * 8 + tig;
                ah[mt][0] = sAhi[base];
                ah[mt][1] = sAhi[base + 8 * ROWU];
                ah[mt][2] = sAhi[base + 4];
                ah[mt][3] = sAhi[base + 8 * ROWU + 4];
                al[mt][0] = sAlo[base];
                al[mt][1] = sAlo[base + 8 * ROWU];
                al[mt][2] = sAlo[base + 4];
                al[mt][3] = sAlo[base + 8 * ROWU + 4];
            }
#pragma unroll
            for (int nt = 0; nt < 8; nt++) {
                int nb = (ncol0 + nt * 8 + g) * ROWU + ks * 8 + tig;
                uint32_t bh0 = sWhi[nb], bh1 = sWhi[nb + 4];
                uint32_t bl0 = sWlo[nb], bl1 = sWlo[nb + 4];
#pragma unroll
                for (int mt = 0; mt < 2; mt++) {
                    mma_bf16(acc[mt][nt], ah[mt], bh0, bh1);
                    mma_bf16(acc[mt][nt], al[mt], bh0, bh1);
                    mma_bf16(acc[mt][nt], ah[mt], bl0, bl1);
                }
            }
        }
        __syncthreads();
    }

    // --- epilogue: tanh + dot(w_w), reduce over h ---
    float sums[2][2] = {{0.f, 0.f}, {0.f, 0.f}};
#pragma unroll
    for (int mt = 0; mt < 2; mt++)
#pragma unroll
        for (int nt = 0; nt < 8; nt++) {
            int hh = ncol0 + nt * 8 + 2 * tig;
            float dv0 = s_dec[hh], dv1 = s_dec[hh + 1];
            float wv0 = s_ww[hh], wv1 = s_ww[hh + 1];
            sums[mt][0] += tanhf(acc[mt][nt][0] + dv0) * wv0
                         + tanhf(acc[mt][nt][1] + dv1) * wv1;
            sums[mt][1] += tanhf(acc[mt][nt][2] + dv0) * wv0
                         + tanhf(acc[mt][nt][3] + dv1) * wv1;
        }
#pragma unroll
    for (int off = 1; off <= 2; off <<= 1) {
#pragma unroll
        for (int mt = 0; mt < 2; mt++) {
            sums[mt][0] += __shfl_xor_sync(0xffffffffu, sums[mt][0], off);
            sums[mt][1] += __shfl_xor_sync(0xffffffffu, sums[mt][1], off);
        }
    }
    if (w < 4 && tig == 0) {
#pragma unroll
        for (int mt = 0; mt < 2; mt++) {
            s_erg[mrow0 + mt * 16 + g] = sums[mt][0];
            s_erg[mrow0 + mt * 16 + 8 + g] = sums[mt][1];
        }
    }
    __syncthreads();
    if (w >= 4 && tig == 0) {
#pragma unroll
        for (int mt = 0; mt < 2; mt++) {
            s_erg[mrow0 + mt * 16 + g] += sums[mt][0];
            s_erg[mrow0 + mt * 16 + 8 + g] += sums[mt][1];
        }
    }
    __syncthreads();
    if (tid < 128)
        g_erg[b * T + t0 + tid] = s_erg[tid] + wbp[0];
}

// ===========================================================================
// k_softmax
// ===========================================================================
__global__ __launch_bounds__(256)
void k_softmax(const int* __restrict__ lens, float* __restrict__ wout) {
    const int b = blockIdx.x;
    const int len = lens[b];
    const int tid = threadIdx.x;
    const int lane = tid & 31, wid = tid >> 5;
    __shared__ float sh[8];

    float m = -INFINITY;
#pragma unroll
    for (int k = 0; k < T / 256; k++) {
        int t = tid + k * 256;
        if (t < len) m = fmaxf(m, g_erg[b * T + t]);
    }
#pragma unroll
    for (int o = 16; o; o >>= 1) m = fmaxf(m, __shfl_xor_sync(0xffffffffu, m, o));
    if (lane == 0) sh[wid] = m;
    __syncthreads();
    m = (lane < 8) ? sh[lane] : -INFINITY;
#pragma unroll
    for (int o = 4; o; o >>= 1) m = fmaxf(m, __shfl_xor_sync(0xffffffffu, m, o));
    if (tid == 0) sh[0] = m;
    __syncthreads();
    m = sh[0];
    __syncthreads();

    float v[T / 256];
    float sum = 0.f;
#pragma unroll
    for (int k = 0; k < T / 256; k++) {
        int t = tid + k * 256;
        v[k] = (t < len) ? expf(g_erg[b * T + t] - m) : 0.f;
        sum += v[k];
    }
#pragma unroll
    for (int o = 16; o; o >>= 1) sum += __shfl_xor_sync(0xffffffffu, sum, o);
    if (lane == 0) sh[wid] = sum;
    __syncthreads();
    sum = (lane < 8) ? sh[lane] : 0.f;
#pragma unroll
    for (int o = 4; o; o >>= 1) sum += __shfl_xor_sync(0xffffffffu, sum, o);
    if (tid == 0) sh[0] = sum;
    __syncthreads();
    const float inv = 1.f / sh[0];

#pragma unroll
    for (int k = 0; k < T / 256; k++) {
        int t = tid + k * 256;
        wout[b * T + t] = v[k] * inv;
    }
}

// ===========================================================================
// context pass
// ===========================================================================
__global__ __launch_bounds__(512)
void k_ctx_part(const float* __restrict__ enc, const float* __restrict__ wgt) {
    const int b = blockIdx.x;
    const int ts = blockIdx.y;
    const int e = threadIdx.x;
    const int t0 = ts * (T / TS);
    __shared__ float sw[T / TS];
    if (threadIdx.x < T / TS)
        sw[threadIdx.x] = wgt[b * T + t0 + threadIdx.x];
    __syncthreads();

    float acc = 0.f;
    const float* p = enc + ((size_t)b * T + t0) * E + e;
#pragma unroll 8
    for (int t = 0; t < T / TS; t++)
        acc = fmaf(sw[t], p[(size_t)t * E], acc);
    g_ctx_part[ts][b][e] = acc;
}

__global__ __launch_bounds__(512)
void k_ctx_reduce(float* __restrict__ ctx) {
    const int b = blockIdx.x;
    const int e = threadIdx.x;
    float s = 0.f;
#pragma unroll
    for (int k = 0; k < TS; k++) s += g_ctx_part[k][b][e];
    ctx[b * E + e] = s;
}

// ===========================================================================
extern "C" void kernel_launch(void* const* d_in, const int* in_sizes, int n_in,
                              void* d_out, int out_size) {
    const float* enc  = (const float*)d_in[0];   // [B,T,E]
    const int*   lens = (const int*)  d_in[1];   // [B]
    const float* ds   = (const float*)d_in[2];   // [B,D]
    // d_in[3] = mask (bool) — rebuilt from src_lens
    const float* Wenc = (const float*)d_in[4];   // [E,H]
    const float* benc = (const float*)d_in[5];   // [H]
    const float* Wdec = (const float*)d_in[6];   // [D,H]
    const float* ww   = (const float*)d_in[7];   // [H,1]
    const float* wb   = (const float*)d_in[8];   // [1]

    float* ctx = (float*)d_out;           // [B,E]
    float* wgt = (float*)d_out + B * E;   // [B,T]

    k_wprep<<<dim3(E / 32, H / 32), dim3(32, 32)>>>(Wenc);
    k_dec<<<B, dim3(128, 8)>>>(ds, Wdec, benc);
    k_erg<<<B * 16, 256>>>(enc, ww, wb);
    k_softmax<<<B, 256>>>(lens, wgt);
    k_ctx_part<<<dim3(B, TS), 512>>>(enc, wgt);
    k_ctx_reduce<<<B, E>>>(ctx);
}